// round 10
// baseline (speedup 1.0000x reference)
#include <cuda_runtime.h>
#include <cuda_bf16.h>
#include <stdint.h>
#include <math.h>

#define B_ 256
#define N_ 31
#define G_ 32
#define T_ 64
#define H_ 128
#define GT_ 2048          // G_*T_
#define XPAD 132
#define QPAD 132

// ---------------- scratch ----------------
__device__ float g_Q[(size_t)B_ * T_ * H_];          // 8 MB
__device__ float g_Kt[(size_t)B_ * H_ * GT_];        // 256 MB, [b][h][key]
__device__ float g_V[(size_t)B_ * GT_ * H_];         // 256 MB, [b][key][h]
__device__ int   g_maskKind;                         // 0=u8/bool, 1=int32, 2=float32

// ---------------------------------------------------------------------------
// Mask dtype sniffer (deterministic function of input bytes)
// ---------------------------------------------------------------------------
__global__ void k_detect_mask(const unsigned* __restrict__ m) {
    __shared__ int okInt, okFloat;
    if (threadIdx.x == 0) { okInt = 1; okFloat = 1; }
    __syncthreads();
    int badI = 0, badF = 0;
    for (int i = threadIdx.x; i < 1024; i += 256) {
        unsigned w = m[i];
        if (!(w == 0u || w == 1u)) badI = 1;
        if (!(w == 0u || w == 0x3F800000u)) badF = 1;
    }
    if (badI) atomicAnd(&okInt, 0);
    if (badF) atomicAnd(&okFloat, 0);
    __syncthreads();
    if (threadIdx.x == 0) g_maskKind = okInt ? 1 : (okFloat ? 2 : 0);
}

// ---------------------------------------------------------------------------
// Kernel 0: Q = node @ Wq (SIMT fp32; small)
// ---------------------------------------------------------------------------
__global__ void __launch_bounds__(256)
k_qproj(const float* __restrict__ node, const float* __restrict__ Wq) {
    extern __shared__ float sm[];
    float* ws = sm;
    float* xs = sm + H_ * H_;
    const int b = blockIdx.x;
    const int tid = threadIdx.x;

    for (int f = tid; f < H_ * H_ / 4; f += 256) {
        int k = f >> 5, j4 = f & 31;
        float4 v = ((const float4*)Wq)[f];
        *(float4*)&ws[k * H_ + j4 * 4] = v;
    }
    const float* src = node + (size_t)b * T_ * H_;
    for (int f = tid; f < T_ * H_ / 4; f += 256) {
        int r = f >> 5, h4 = f & 31;
        float4 v = ((const float4*)src)[f];
        *(float4*)&xs[r * XPAD + h4 * 4] = v;
    }
    __syncthreads();

    const int trow = tid >> 5;
    const int tcol = tid & 31;
    float acc[8][4];
#pragma unroll
    for (int i = 0; i < 8; i++)
#pragma unroll
        for (int j = 0; j < 4; j++) acc[i][j] = 0.f;

    for (int k0 = 0; k0 < H_; k0 += 4) {
        float xr[8][4];
#pragma unroll
        for (int i = 0; i < 8; i++) {
            float4 v = *(float4*)&xs[(trow * 8 + i) * XPAD + k0];
            xr[i][0] = v.x; xr[i][1] = v.y; xr[i][2] = v.z; xr[i][3] = v.w;
        }
#pragma unroll
        for (int kk = 0; kk < 4; kk++) {
            float4 w = *(float4*)&ws[(k0 + kk) * H_ + tcol * 4];
#pragma unroll
            for (int i = 0; i < 8; i++) {
                acc[i][0] += xr[i][kk] * w.x;
                acc[i][1] += xr[i][kk] * w.y;
                acc[i][2] += xr[i][kk] * w.z;
                acc[i][3] += xr[i][kk] * w.w;
            }
        }
    }
#pragma unroll
    for (int i = 0; i < 8; i++) {
        int row = trow * 8 + i;
        *(float4*)&g_Q[((size_t)b * T_ + row) * H_ + tcol * 4] =
            make_float4(acc[i][0], acc[i][1], acc[i][2], acc[i][3]);
    }
}

// ---------------------------------------------------------------------------
// Kernel 1: K / V projection via mma.sync bf16 (bf16x3 split).
// Grid (32, B): blockIdx.x = tile*2 + kv.  Tile = 128 keys (2 groups).
// C = X[128,128] @ W^T[n=128,k=128].  Warp tile 32x64 (2x8 m16n8k16 frags).
// ---------------------------------------------------------------------------
#define WS_ 136                      // bf16 row stride for W/X smem tiles
#define OFF_WH 0
#define OFF_WL 34816
#define OFF_XH 69632
#define OFF_XL 104448
#define SMEM_KVM 139264              // bytes

__device__ __forceinline__ void mma16816(float* c, const uint32_t* a, const uint32_t* b) {
    asm volatile(
        "mma.sync.aligned.m16n8k16.row.col.f32.bf16.bf16.f32 "
        "{%0,%1,%2,%3}, {%4,%5,%6,%7}, {%8,%9}, {%0,%1,%2,%3};"
        : "+f"(c[0]), "+f"(c[1]), "+f"(c[2]), "+f"(c[3])
        : "r"(a[0]), "r"(a[1]), "r"(a[2]), "r"(a[3]), "r"(b[0]), "r"(b[1]));
}

__global__ void __launch_bounds__(256, 1)
k_kv_mma(const float* __restrict__ node, const float* __restrict__ neigh,
         const float* __restrict__ Wk, const float* __restrict__ Wv) {
    extern __shared__ char smc[];
    uint16_t* wh = (uint16_t*)(smc + OFF_WH);
    uint16_t* wl = (uint16_t*)(smc + OFF_WL);
    uint16_t* xh = (uint16_t*)(smc + OFF_XH);
    uint16_t* xl = (uint16_t*)(smc + OFF_XL);

    const int tid = threadIdx.x;
    const int b = blockIdx.y;
    const int t = blockIdx.x >> 1;       // key tile (128 keys): groups 2t, 2t+1
    const int kv = blockIdx.x & 1;       // 0=K, 1=V
    const float* W = kv ? Wv : Wk;

    // Stage W^T: wh/wl[n][k] <- W[k*H + n] (coalesced global reads)
    for (int f = tid; f < H_ * H_; f += 256) {
        int k = f >> 7, n = f & 127;
        float w = W[f];
        __nv_bfloat16 hb = __float2bfloat16_rn(w);
        float lo = w - __bfloat162float(hb);
        __nv_bfloat16 lb = __float2bfloat16_rn(lo);
        wh[n * WS_ + k] = __bfloat16_as_ushort(hb);
        wl[n * WS_ + k] = __bfloat16_as_ushort(lb);
    }

    // Stage X: xh/xl[m][k], m = key within tile
    for (int f = tid; f < 4096; f += 256) {
        int m = f >> 5, c4 = f & 31;
        int g = (t << 1) + (m >> 6), row = m & 63;
        const float* src = (g == 0)
            ? node + ((size_t)b * T_ + row) * H_
            : neigh + (((size_t)b * N_ + (g - 1)) * T_ + row) * H_;
        float4 x = ((const float4*)src)[c4];
        __nv_bfloat16 h0 = __float2bfloat16_rn(x.x);
        __nv_bfloat16 h1 = __float2bfloat16_rn(x.y);
        __nv_bfloat16 h2 = __float2bfloat16_rn(x.z);
        __nv_bfloat16 h3 = __float2bfloat16_rn(x.w);
        __nv_bfloat16 l0 = __float2bfloat16_rn(x.x - __bfloat162float(h0));
        __nv_bfloat16 l1 = __float2bfloat16_rn(x.y - __bfloat162float(h1));
        __nv_bfloat16 l2 = __float2bfloat16_rn(x.z - __bfloat162float(h2));
        __nv_bfloat16 l3 = __float2bfloat16_rn(x.w - __bfloat162float(h3));
        int c = c4 * 4;
        uint32_t* ph = (uint32_t*)&xh[m * WS_ + c];
        uint32_t* pl = (uint32_t*)&xl[m * WS_ + c];
        ph[0] = (uint32_t)__bfloat16_as_ushort(h0) | ((uint32_t)__bfloat16_as_ushort(h1) << 16);
        ph[1] = (uint32_t)__bfloat16_as_ushort(h2) | ((uint32_t)__bfloat16_as_ushort(h3) << 16);
        pl[0] = (uint32_t)__bfloat16_as_ushort(l0) | ((uint32_t)__bfloat16_as_ushort(l1) << 16);
        pl[1] = (uint32_t)__bfloat16_as_ushort(l2) | ((uint32_t)__bfloat16_as_ushort(l3) << 16);
    }
    __syncthreads();

    const int wid = tid >> 5, lane = tid & 31;
    const int wm = wid >> 1, wn = wid & 1;     // warp tile: rows 32*wm, cols 64*wn
    const int gq = lane >> 2, tg = lane & 3;

    float c[2][8][4];
#pragma unroll
    for (int mt = 0; mt < 2; mt++)
#pragma unroll
        for (int nt = 0; nt < 8; nt++)
#pragma unroll
            for (int r = 0; r < 4; r++) c[mt][nt][r] = 0.f;

#pragma unroll
    for (int ks = 0; ks < 8; ks++) {
        const int k0 = ks * 16;
        uint32_t a[2][4], al[2][4], bh[8][2], bl[8][2];
#pragma unroll
        for (int mt = 0; mt < 2; mt++) {
            int row = wm * 32 + mt * 16 + gq;
            int col = k0 + tg * 2;
            a[mt][0]  = *(uint32_t*)&xh[row * WS_ + col];
            a[mt][1]  = *(uint32_t*)&xh[(row + 8) * WS_ + col];
            a[mt][2]  = *(uint32_t*)&xh[row * WS_ + col + 8];
            a[mt][3]  = *(uint32_t*)&xh[(row + 8) * WS_ + col + 8];
            al[mt][0] = *(uint32_t*)&xl[row * WS_ + col];
            al[mt][1] = *(uint32_t*)&xl[(row + 8) * WS_ + col];
            al[mt][2] = *(uint32_t*)&xl[row * WS_ + col + 8];
            al[mt][3] = *(uint32_t*)&xl[(row + 8) * WS_ + col + 8];
        }
#pragma unroll
        for (int nt = 0; nt < 8; nt++) {
            int n = wn * 64 + nt * 8 + gq;
            int col = k0 + tg * 2;
            bh[nt][0] = *(uint32_t*)&wh[n * WS_ + col];
            bh[nt][1] = *(uint32_t*)&wh[n * WS_ + col + 8];
            bl[nt][0] = *(uint32_t*)&wl[n * WS_ + col];
            bl[nt][1] = *(uint32_t*)&wl[n * WS_ + col + 8];
        }
#pragma unroll
        for (int mt = 0; mt < 2; mt++)
#pragma unroll
            for (int nt = 0; nt < 8; nt++) {
                mma16816(c[mt][nt], a[mt], bh[nt]);
                mma16816(c[mt][nt], a[mt], bl[nt]);
                mma16816(c[mt][nt], al[mt], bh[nt]);
            }
    }
    __syncthreads();   // tiles no longer needed; reuse smem as fp32 staging

    float* st = (float*)smc;   // [128][132]
    if (kv == 0) {
        // K: stage transposed st[n][m]
#pragma unroll
        for (int mt = 0; mt < 2; mt++)
#pragma unroll
            for (int nt = 0; nt < 8; nt++) {
                int row = wm * 32 + mt * 16 + gq;
                int col = wn * 64 + nt * 8 + tg * 2;
                st[col * XPAD + row]           = c[mt][nt][0];
                st[(col + 1) * XPAD + row]     = c[mt][nt][1];
                st[col * XPAD + row + 8]       = c[mt][nt][2];
                st[(col + 1) * XPAD + row + 8] = c[mt][nt][3];
            }
        __syncthreads();
        for (int f = tid; f < 128 * 32; f += 256) {
            int h = f >> 5, m4 = f & 31;
            float4 v = *(const float4*)&st[h * XPAD + m4 * 4];
            *(float4*)&g_Kt[((size_t)b * H_ + h) * GT_ + t * 128 + m4 * 4] = v;
        }
    } else {
        // V: stage row-major st[m][n]
#pragma unroll
        for (int mt = 0; mt < 2; mt++)
#pragma unroll
            for (int nt = 0; nt < 8; nt++) {
                int row = wm * 32 + mt * 16 + gq;
                int col = wn * 64 + nt * 8 + tg * 2;
                st[row * XPAD + col]           = c[mt][nt][0];
                st[row * XPAD + col + 1]       = c[mt][nt][1];
                st[(row + 8) * XPAD + col]     = c[mt][nt][2];
                st[(row + 8) * XPAD + col + 1] = c[mt][nt][3];
            }
        __syncthreads();
        for (int f = tid; f < 128 * 32; f += 256) {
            int r = f >> 5, h4 = f & 31;
            float4 v = *(const float4*)&st[r * XPAD + h4 * 4];
            *(float4*)&g_V[((size_t)b * GT_ + t * 128 + r) * H_ + h4 * 4] = v;
        }
    }
}

// ---------------------------------------------------------------------------
// Kernel 2: attention per batch. Phase A stores exp(S) (masked -> 0) to the A
// region and accumulates rowsums; Phase C only scales by 1/l (no second exp).
// ---------------------------------------------------------------------------
__global__ void __launch_bounds__(256, 2)
k_attn(const void* __restrict__ mask, float* __restrict__ out) {
    extern __shared__ float sm[];
    float* qs = sm;                          // [64][QPAD]
    float* ks = sm + T_ * QPAD;              // [128][128]
    float* red = ks + H_ * H_;               // [64*16]
    float* invl = red + T_ * 16;             // [64]
    unsigned char* ms = (unsigned char*)(invl + T_);  // [64*64]

    const int b = blockIdx.x;
    const int tid = threadIdx.x;
    const int tq = tid >> 4;
    const int tk = tid & 15;

    float* Ab = out + (size_t)B_ * T_ * H_ + (size_t)b * T_ * GT_;

    const float* qg = g_Q + (size_t)b * T_ * H_;
    for (int f = tid; f < T_ * H_ / 4; f += 256) {
        int r = f >> 5, h4 = f & 31;
        *(float4*)&qs[r * QPAD + h4 * 4] = ((const float4*)qg)[f];
    }
    {
        const size_t base = (size_t)b * T_ * T_;
        const int kind = g_maskKind;
        if (kind == 1) {
            const int* mg = (const int*)mask + base;
            for (int f = tid; f < T_ * T_; f += 256) ms[f] = (unsigned char)(mg[f] != 0);
        } else if (kind == 2) {
            const float* mg = (const float*)mask + base;
            for (int f = tid; f < T_ * T_; f += 256) ms[f] = (unsigned char)(mg[f] != 0.0f);
        } else {
            const unsigned char* mg = (const unsigned char*)mask + base;
            for (int f = tid; f < T_ * T_; f += 256) ms[f] = mg[f];
        }
    }
    __syncthreads();

    unsigned mbits[4];
#pragma unroll
    for (int i = 0; i < 4; i++) {
        int q = tq * 4 + i;
        unsigned m = 0;
#pragma unroll
        for (int j = 0; j < 8; j++) {
            int col = (tk * 8 + j) & 63;
            if (ms[q * 64 + col]) m |= (1u << j);
        }
        mbits[i] = m;
    }

    float lsum[4] = {0.f, 0.f, 0.f, 0.f};
    const float* ktg = g_Kt + (size_t)b * H_ * GT_;

    for (int c = 0; c < 16; c++) {
        __syncthreads();
        for (int f = tid; f < H_ * 128 / 4; f += 256) {
            int h = f >> 5, k4 = f & 31;
            *(float4*)&ks[h * 128 + k4 * 4] =
                *(const float4*)&ktg[(size_t)h * GT_ + c * 128 + k4 * 4];
        }
        __syncthreads();

        float sc[4][8];
#pragma unroll
        for (int i = 0; i < 4; i++)
#pragma unroll
            for (int j = 0; j < 8; j++) sc[i][j] = 0.f;

        for (int h0 = 0; h0 < H_; h0 += 4) {
            float qr[4][4];
#pragma unroll
            for (int i = 0; i < 4; i++) {
                float4 v = *(float4*)&qs[(tq * 4 + i) * QPAD + h0];
                qr[i][0] = v.x; qr[i][1] = v.y; qr[i][2] = v.z; qr[i][3] = v.w;
            }
#pragma unroll
            for (int hh = 0; hh < 4; hh++) {
                float4 k0v = *(float4*)&ks[(h0 + hh) * 128 + tk * 8];
                float4 k1v = *(float4*)&ks[(h0 + hh) * 128 + tk * 8 + 4];
                float kr[8] = {k0v.x, k0v.y, k0v.z, k0v.w, k1v.x, k1v.y, k1v.z, k1v.w};
#pragma unroll
                for (int i = 0; i < 4; i++)
#pragma unroll
                    for (int j = 0; j < 8; j++)
                        sc[i][j] += qr[i][hh] * kr[j];
            }
        }
#pragma unroll
        for (int i = 0; i < 4; i++) {
            int q = tq * 4 + i;
#pragma unroll
            for (int j = 0; j < 8; j++) {
                float e = ((mbits[i] >> j) & 1) ? 0.0f : __expf(sc[i][j]);
                lsum[i] += e;
                sc[i][j] = e;
            }
            float* dst = &Ab[(size_t)q * GT_ + c * 128 + tk * 8];
            *(float4*)dst       = make_float4(sc[i][0], sc[i][1], sc[i][2], sc[i][3]);
            *(float4*)(dst + 4) = make_float4(sc[i][4], sc[i][5], sc[i][6], sc[i][7]);
        }
    }

#pragma unroll
    for (int i = 0; i < 4; i++) red[(tq * 4 + i) * 16 + tk] = lsum[i];
    __syncthreads();
    if (tid < 64) {
        float s = 0.f;
#pragma unroll
        for (int t = 0; t < 16; t++) s += red[tid * 16 + t];
        invl[tid] = 1.0f / s;
    }

    // Phase C: scale + PV
    float* ps = qs;
    float* vs = ks;
    const float* vg = g_V + (size_t)b * GT_ * H_;
    const int th = tk;

    float oacc[4][8];
#pragma unroll
    for (int i = 0; i < 4; i++)
#pragma unroll
        for (int j = 0; j < 8; j++) oacc[i][j] = 0.f;

    for (int c = 0; c < 16; c++) {
        __syncthreads();
        for (int f = tid; f < 128 * H_ / 4; f += 256) {
            int key = f >> 5, h4 = f & 31;
            *(float4*)&vs[key * 128 + h4 * 4] =
                *(const float4*)&vg[((size_t)(c * 128 + key)) * H_ + h4 * 4];
        }
        for (int f = tid; f < T_ * 128 / 4; f += 256) {
            int q = f >> 5, k4 = f & 31;
            float* gaddr = &Ab[(size_t)q * GT_ + c * 128 + k4 * 4];
            float4 v = *(float4*)gaddr;
            float il = invl[q];
            v.x *= il; v.y *= il; v.z *= il; v.w *= il;
            *(float4*)gaddr = v;
            *(float4*)&ps[q * QPAD + k4 * 4] = v;
        }
        __syncthreads();

        for (int kk0 = 0; kk0 < 128; kk0 += 4) {
            float pr[4][4];
#pragma unroll
            for (int i = 0; i < 4; i++) {
                float4 v = *(float4*)&ps[(tq * 4 + i) * QPAD + kk0];
                pr[i][0] = v.x; pr[i][1] = v.y; pr[i][2] = v.z; pr[i][3] = v.w;
            }
#pragma unroll
            for (int u = 0; u < 4; u++) {
                float4 v0 = *(float4*)&vs[(kk0 + u) * 128 + th * 8];
                float4 v1 = *(float4*)&vs[(kk0 + u) * 128 + th * 8 + 4];
                float vr[8] = {v0.x, v0.y, v0.z, v0.w, v1.x, v1.y, v1.z, v1.w};
#pragma unroll
                for (int i = 0; i < 4; i++)
#pragma unroll
                    for (int j = 0; j < 8; j++)
                        oacc[i][j] += pr[i][u] * vr[j];
            }
        }
    }

#pragma unroll
    for (int i = 0; i < 4; i++) {
        int q = tq * 4 + i;
        float* dst = &out[((size_t)b * T_ + q) * H_ + th * 8];
        *(float4*)dst       = make_float4(oacc[i][0], oacc[i][1], oacc[i][2], oacc[i][3]);
        *(float4*)(dst + 4) = make_float4(oacc[i][4], oacc[i][5], oacc[i][6], oacc[i][7]);
    }
}

// ---------------------------------------------------------------------------
static const int SMEM_Q  = (H_ * H_ + T_ * XPAD) * 4;
static const int SMEM_AT = (T_ * QPAD + H_ * H_ + T_ * 16 + T_) * 4 + T_ * T_;

extern "C" void kernel_launch(void* const* d_in, const int* in_sizes, int n_in,
                              void* d_out, int out_size) {
    (void)in_sizes; (void)n_in; (void)out_size;
    const float* node  = (const float*)d_in[0];
    const float* neigh = (const float*)d_in[1];
    const void*  mask  = d_in[2];
    const float* Wq = (const float*)d_in[3];
    const float* Wk = (const float*)d_in[4];
    const float* Wv = (const float*)d_in[5];
    float* out = (float*)d_out;

    static bool inited = false;
    if (!inited) {
        cudaFuncSetAttribute(k_qproj,   cudaFuncAttributeMaxDynamicSharedMemorySize, SMEM_Q);
        cudaFuncSetAttribute(k_kv_mma,  cudaFuncAttributeMaxDynamicSharedMemorySize, SMEM_KVM);
        cudaFuncSetAttribute(k_attn,    cudaFuncAttributeMaxDynamicSharedMemorySize, SMEM_AT);
        inited = true;
    }

    k_detect_mask<<<1, 256>>>((const unsigned*)mask);
    k_qproj<<<B_, 256, SMEM_Q>>>(node, Wq);
    k_kv_mma<<<dim3(32, B_), 256, SMEM_KVM>>>(node, neigh, Wk, Wv);
    k_attn<<<B_, 256, SMEM_AT>>>(mask, out);
}